// round 16
// baseline (speedup 1.0000x reference)
#include <cuda_runtime.h>
#include <cuda_fp16.h>
#include <math.h>
#include <cstdint>

#define BB   8192
#define DVV  768
#define NE   8
#define DD   1024
#define GG   2048

// GEMM tiling: CTA 128x256, 8 warps of 64x64, BK=128 halves, 2-stage cp.async
#define BM 128
#define BN 256
#define BK 128
#define STAGES 2
#define PADH 136                        // halves per row; 272B stride, conflict-free
#define STAGE_HALVES ((BM + BN) * PADH)
#define SMEM_BYTES (STAGES * STAGE_HALVES * 2)

// 32-group K-permutation: thread c's fragments for TWO k16 steps are 16B-contiguous.
__host__ __device__ __forceinline__ int kperm32(int k) {
    return (k & ~31) | (((k >> 1) & 3) << 3) | (((k >> 4) & 1) << 2)
         | (((k >> 3) & 1) << 1) | (k & 1);
}

// ---------------------------------------------------------------------------
// Scratch (static device globals). GEMM operands stored as k-permuted fp16.
// ---------------------------------------------------------------------------
__device__ __half g_inr[(size_t)2 * BB * DVV];
__device__ __half g_pwT[(size_t)2 * DVV * DD];
__device__ float  g_pbias[2 * DD];
__device__ __half g_w1T[(size_t)NE * GG * DD];
__device__ __half g_w2T[(size_t)NE * DD * DD];
__device__ __half g_combined[(size_t)BB * GG];
__device__ float  g_gate[BB * NE];
__device__ __half g_h[(size_t)BB * NE * DD];
__device__ __half g_t[(size_t)BB * NE * DD];      // fp16 (normal layout)

// ---------------------------------------------------------------------------
// Helpers
// ---------------------------------------------------------------------------
__device__ __forceinline__ uint32_t smem_u32(const void* p) {
    uint32_t a;
    asm("{ .reg .u64 t; cvta.to.shared.u64 t, %1; cvt.u32.u64 %0, t; }" : "=r"(a) : "l"(p));
    return a;
}
__device__ __forceinline__ void cp_async16(uint32_t dst, const void* src) {
    asm volatile("cp.async.cg.shared.global [%0], [%1], 16;" :: "r"(dst), "l"(src));
}
#define CP_COMMIT() asm volatile("cp.async.commit_group;" ::: "memory")
#define CP_WAIT(n)  asm volatile("cp.async.wait_group %0;" :: "n"(n) : "memory")

__device__ __forceinline__ void mma_f16(float& c0, float& c1, float& c2, float& c3,
                                        uint32_t a0, uint32_t a1, uint32_t a2, uint32_t a3,
                                        uint32_t b0, uint32_t b1) {
    asm volatile(
        "mma.sync.aligned.m16n8k16.row.col.f32.f16.f16.f32 "
        "{%0,%1,%2,%3}, {%4,%5,%6,%7}, {%8,%9}, {%0,%1,%2,%3};\n"
        : "+f"(c0), "+f"(c1), "+f"(c2), "+f"(c3)
        : "r"(a0), "r"(a1), "r"(a2), "r"(a3), "r"(b0), "r"(b1));
}

// ---------------------------------------------------------------------------
// fp16 tensor-core GEMM: C[m,n] = act( sum_k A[m,k]*B[n,k] + bias[n] )
// A [M,K] row-major, B [N,K] K-major, both kperm32 fp16.
// CTA 128x256, warp grid 2(m) x 4(n), warp tile 64x64, BK=128, 2-stage.
// mode 0: store half(v) kperm cols; mode 1: half(gelu(v)) kperm cols;
// mode 2: store half(v) NORMAL cols (feeds LN)
// ---------------------------------------------------------------------------
__global__ __launch_bounds__(256, 1)
void f16_gemm(const __half* __restrict__ A, long aBatch, int lda,
              const __half* __restrict__ B, long bBatch, int ldb,
              const float* __restrict__ bias, long biasBatch,
              int K, int mode,
              __half* __restrict__ Ch,
              long cBatch, int ldc, int colOfs, int colStride)
{
    extern __shared__ __half smem[];
    const int tid  = threadIdx.x;
    const int wid  = tid >> 5;
    const int lane = tid & 31;
    const int e    = blockIdx.z;
    const int blockRow = blockIdx.y * BM;
    const int blockCol = blockIdx.x * BN;

    A    += (long)e * aBatch;
    B    += (long)e * bBatch;
    bias += (long)e * biasBatch;
    Ch   += (long)e * cBatch;
    const int cOfs = colOfs + e * colStride;

    const uint32_t smem_base = smem_u32(smem);

    // warp grid: 2 (m) x 4 (n); warp tile 64x64
    const int warpRow = (wid & 1) * 64;
    const int warpCol = (wid >> 1) * 64;
    const int groupID = lane >> 2;
    const int ctig    = lane & 3;

    float acc[4][8][4];
    #pragma unroll
    for (int i = 0; i < 4; i++)
        #pragma unroll
        for (int j = 0; j < 8; j++)
            #pragma unroll
            for (int r = 0; r < 4; r++) acc[i][j][r] = 0.0f;

    const int NC = K / BK;

    // loader: chunks per row = BK/8 = 16.  lm 0..15, lk 0..15.
    // A: 128 rows x 16 chunks = 2048 chunks -> 8/thread (row stride 16)
    // B: 256 rows x 16 chunks = 4096 chunks -> 16/thread
    const int lm = tid >> 4, lk = tid & 15;
    const __half* aSrc = A + (long)(blockRow + lm) * lda + lk * 8;
    const __half* bSrc = B + (long)(blockCol + lm) * ldb + lk * 8;
    const uint32_t dstOfs = (uint32_t)(lm * PADH + lk * 8) * 2u;

    auto load_stage = [&](int stage, int chunk) {
        const int k0 = chunk * BK;
        const uint32_t aBase = smem_base + (uint32_t)(stage * STAGE_HALVES) * 2u + dstOfs;
        const uint32_t bBase = aBase + (uint32_t)(BM * PADH) * 2u;
        #pragma unroll
        for (int i = 0; i < 8; i++)
            cp_async16(aBase + (uint32_t)(i * 16 * PADH) * 2u,
                       aSrc + (long)(i * 16) * lda + k0);
        #pragma unroll
        for (int i = 0; i < 16; i++)
            cp_async16(bBase + (uint32_t)(i * 16 * PADH) * 2u,
                       bSrc + (long)(i * 16) * ldb + k0);
        CP_COMMIT();
    };

    #pragma unroll
    for (int s = 0; s < STAGES - 1; s++) load_stage(s, s);
    CP_WAIT(STAGES - 2);
    __syncthreads();

    for (int c = 0; c < NC; c++) {
        if (c + STAGES - 1 < NC)
            load_stage((c + STAGES - 1) % STAGES, c + STAGES - 1);

        const int stage = c % STAGES;
        const __half* As = smem + stage * STAGE_HALVES;
        const __half* Bs = As + BM * PADH;

        #pragma unroll
        for (int pr = 0; pr < 4; pr++) {          // four k32-pairs per BK=128
            const int kb = pr * 32 + 8 * ctig;
            uint4 alo[4], ahi[4], bv[8];
            #pragma unroll
            for (int i = 0; i < 4; i++) {
                const __half* p = As + (warpRow + i * 16 + groupID) * PADH + kb;
                alo[i] = *reinterpret_cast<const uint4*>(p);
                ahi[i] = *reinterpret_cast<const uint4*>(p + 8 * PADH);
            }
            #pragma unroll
            for (int j = 0; j < 8; j++)
                bv[j] = *reinterpret_cast<const uint4*>(
                            Bs + (warpCol + j * 8 + groupID) * PADH + kb);
            #pragma unroll
            for (int i = 0; i < 4; i++)
                #pragma unroll
                for (int j = 0; j < 8; j++) {
                    mma_f16(acc[i][j][0], acc[i][j][1], acc[i][j][2], acc[i][j][3],
                            alo[i].x, ahi[i].x, alo[i].y, ahi[i].y,
                            bv[j].x, bv[j].y);
                    mma_f16(acc[i][j][0], acc[i][j][1], acc[i][j][2], acc[i][j][3],
                            alo[i].z, ahi[i].z, alo[i].w, ahi[i].w,
                            bv[j].z, bv[j].w);
                }
        }

        CP_WAIT(STAGES - 2);
        __syncthreads();
    }

    // ---- epilogue ----
    #pragma unroll
    for (int i = 0; i < 4; i++) {
        const int r0 = blockRow + warpRow + i * 16 + groupID;
        #pragma unroll
        for (int j = 0; j < 8; j++) {
            const int gc = blockCol + warpCol + j * 8 + ctig * 2;
            const float b0 = bias[gc], b1 = bias[gc + 1];
            float v0 = acc[i][j][0] + b0;
            float v1 = acc[i][j][1] + b1;
            float v2 = acc[i][j][2] + b0;
            float v3 = acc[i][j][3] + b1;
            if (mode == 2) {
                *reinterpret_cast<__half2*>(Ch + (long)r0 * ldc + cOfs + gc) =
                    __floats2half2_rn(v0, v1);
                *reinterpret_cast<__half2*>(Ch + (long)(r0 + 8) * ldc + cOfs + gc) =
                    __floats2half2_rn(v2, v3);
            } else {
                if (mode == 1) {
                    v0 = 0.5f * v0 * (1.0f + erff(v0 * 0.70710678118654752f));
                    v1 = 0.5f * v1 * (1.0f + erff(v1 * 0.70710678118654752f));
                    v2 = 0.5f * v2 * (1.0f + erff(v2 * 0.70710678118654752f));
                    v3 = 0.5f * v3 * (1.0f + erff(v3 * 0.70710678118654752f));
                }
                const int cp0 = kperm32(cOfs + gc);
                *reinterpret_cast<__half2*>(Ch + (long)r0 * ldc + cp0) =
                    __floats2half2_rn(v0, v1);
                *reinterpret_cast<__half2*>(Ch + (long)(r0 + 8) * ldc + cp0) =
                    __floats2half2_rn(v2, v3);
            }
        }
    }
}

// ---------------------------------------------------------------------------
// Fused prep: convert both inputs to kperm32 fp16, pack proj biases.
// ---------------------------------------------------------------------------
__global__ void prep_kernel(const float* __restrict__ visual,
                            const float* __restrict__ text,
                            const float* __restrict__ vis_b,
                            const float* __restrict__ txt_b,
                            __half* __restrict__ inr,
                            float* __restrict__ pbias)
{
    const long nPer = (long)BB * DVV;
    long t = (long)blockIdx.x * blockDim.x + threadIdx.x;
    if (t < 2 * DD)
        pbias[t] = (t < DD) ? vis_b[t] : txt_b[t - DD];
    long i = t * 32;
    if (i >= 2 * nPer) return;
    const float* src = (i < nPer) ? (visual + i) : (text + (i - nPer));
    float lv[32];
    #pragma unroll
    for (int q = 0; q < 8; q++)
        *reinterpret_cast<float4*>(lv + q * 4) =
            *reinterpret_cast<const float4*>(src + q * 4);
    __half ph[32];
    #pragma unroll
    for (int q = 0; q < 32; q++)
        ph[kperm32(q)] = __float2half_rn(lv[q]);
    #pragma unroll
    for (int q = 0; q < 4; q++)
        *reinterpret_cast<uint4*>(inr + i + q * 8) =
            *reinterpret_cast<uint4*>(ph + q * 8);
}

// ---------------------------------------------------------------------------
// W [K,N] fp32 -> WT [N,K] fp16 kperm32; z selects source
// ---------------------------------------------------------------------------
__global__ __launch_bounds__(256)
void transpose_kernel(const float* __restrict__ W0,
                      const float* __restrict__ W1,
                      __half* __restrict__ WT, int K, int N)
{
    __shared__ float tile[32][33];
    const int e = blockIdx.z;
    const float* W = (W1 == nullptr) ? (W0 + (long)e * K * N)
                                     : (e == 0 ? W0 : W1);
    __half* WTe = WT + (long)e * K * N;
    const int n0 = blockIdx.x * 32, k0 = blockIdx.y * 32;
    const int tx = threadIdx.x & 31, ty = threadIdx.x >> 5;

    #pragma unroll
    for (int r = 0; r < 4; r++)
        tile[ty + r * 8][tx] = W[(long)(k0 + ty + r * 8) * N + n0 + tx];
    __syncthreads();
    #pragma unroll
    for (int r = 0; r < 4; r++) {
        int n = n0 + ty + r * 8, k = k0 + tx;
        WTe[(long)n * K + kperm32(k)] = __float2half_rn(tile[tx][ty + r * 8]);
    }
}

// ---------------------------------------------------------------------------
// Gate: one warp per row (combined fp16 kperm32; gw logical index)
// ---------------------------------------------------------------------------
__global__ void gate_kernel(const __half* __restrict__ combined,
                            const float* __restrict__ gw,
                            const float* __restrict__ gb,
                            float* __restrict__ gate)
{
    int warp = (blockIdx.x * blockDim.x + threadIdx.x) >> 5;
    int lane = threadIdx.x & 31;
    if (warp >= BB) return;
    const __half* row = combined + (long)warp * GG;

    float acc[NE];
    #pragma unroll
    for (int e = 0; e < NE; e++) acc[e] = 0.0f;

    for (int k = lane; k < GG; k += 32) {
        float x = __half2float(row[kperm32(k)]);
        const float4 w0 = *reinterpret_cast<const float4*>(gw + (long)k * NE);
        const float4 w1 = *reinterpret_cast<const float4*>(gw + (long)k * NE + 4);
        acc[0] = fmaf(x, w0.x, acc[0]);
        acc[1] = fmaf(x, w0.y, acc[1]);
        acc[2] = fmaf(x, w0.z, acc[2]);
        acc[3] = fmaf(x, w0.w, acc[3]);
        acc[4] = fmaf(x, w1.x, acc[4]);
        acc[5] = fmaf(x, w1.y, acc[5]);
        acc[6] = fmaf(x, w1.z, acc[6]);
        acc[7] = fmaf(x, w1.w, acc[7]);
    }
    #pragma unroll
    for (int e = 0; e < NE; e++)
        #pragma unroll
        for (int o = 16; o > 0; o >>= 1)
            acc[e] += __shfl_xor_sync(0xFFFFFFFFu, acc[e], o);

    float m = -1e30f;
    #pragma unroll
    for (int e = 0; e < NE; e++) { acc[e] += gb[e]; m = fmaxf(m, acc[e]); }
    float s = 0.0f;
    #pragma unroll
    for (int e = 0; e < NE; e++) { acc[e] = expf(acc[e] - m); s += acc[e]; }
    float inv = 1.0f / s;
    if (lane < NE) gate[(long)warp * NE + lane] = acc[lane] * inv;
}

// ---------------------------------------------------------------------------
// LayerNorm per (b,e) row + gated reduction over experts (t fp16, normal)
// ---------------------------------------------------------------------------
__global__ __launch_bounds__(256)
void ln_reduce_kernel(const __half* __restrict__ t,
                      const float* __restrict__ gate,
                      const float* __restrict__ ln_g,
                      const float* __restrict__ ln_b,
                      float* __restrict__ out)
{
    const int b = blockIdx.x;
    const int tid = threadIdx.x;
    const int wid = tid >> 5, lane = tid & 31;

    __shared__ float sm_s[8];
    __shared__ float sm_ss[8];

    float o[4] = {0.f, 0.f, 0.f, 0.f};

    for (int e = 0; e < NE; e++) {
        const __half* row = t + ((long)b * NE + e) * DD;
        uint2 raw = *reinterpret_cast<const uint2*>(row + tid * 4);
        float2 f01 = __half22float2(*reinterpret_cast<__half2*>(&raw.x));
        float2 f23 = __half22float2(*reinterpret_cast<__half2*>(&raw.y));
        float xv[4] = {f01.x, f01.y, f23.x, f23.y};
        float s  = xv[0] + xv[1] + xv[2] + xv[3];
        float ss = xv[0]*xv[0] + xv[1]*xv[1] + xv[2]*xv[2] + xv[3]*xv[3];
        #pragma unroll
        for (int o2 = 16; o2 > 0; o2 >>= 1) {
            s  += __shfl_xor_sync(0xFFFFFFFFu, s, o2);
            ss += __shfl_xor_sync(0xFFFFFFFFu, ss, o2);
        }
        if (lane == 0) { sm_s[wid] = s; sm_ss[wid] = ss; }
        __syncthreads();
        float ts = 0.f, tss = 0.f;
        #pragma unroll
        for (int w = 0; w < 8; w++) { ts += sm_s[w]; tss += sm_ss[w]; }
        __syncthreads();

        float mu   = ts * (1.0f / DD);
        float var  = tss * (1.0f / DD) - mu * mu;
        float rstd = rsqrtf(var + 1e-5f);
        float p    = gate[(long)b * NE + e];

        const float4 g4 = *reinterpret_cast<const float4*>(ln_g + (long)e * DD + tid * 4);
        const float4 b4 = *reinterpret_cast<const float4*>(ln_b + (long)e * DD + tid * 4);
        const float* gv = &g4.x;
        const float* bv = &b4.x;
        #pragma unroll
        for (int j = 0; j < 4; j++) {
            float n = (xv[j] - mu) * rstd;
            o[j] = fmaf(p, fmaf(n, gv[j], bv[j]), o[j]);
        }
    }
    *reinterpret_cast<float4*>(out + (long)b * DD + tid * 4) =
        make_float4(o[0], o[1], o[2], o[3]);
}

// ---------------------------------------------------------------------------
// Launch.  The 4th launch is the projection GEMM (the one ncu captures).
// ---------------------------------------------------------------------------
extern "C" void kernel_launch(void* const* d_in, const int* in_sizes, int n_in,
                              void* d_out, int out_size)
{
    const float* visual = (const float*)d_in[0];
    const float* text   = (const float*)d_in[1];
    const float* vis_w  = (const float*)d_in[2];
    const float* vis_b  = (const float*)d_in[3];
    const float* txt_w  = (const float*)d_in[4];
    const float* txt_b  = (const float*)d_in[5];
    const float* gate_w = (const float*)d_in[6];
    const float* gate_b = (const float*)d_in[7];
    const float* w1     = (const float*)d_in[8];
    const float* b1     = (const float*)d_in[9];
    const float* w2     = (const float*)d_in[10];
    const float* b2     = (const float*)d_in[11];
    const float* ln_g   = (const float*)d_in[12];
    const float* ln_b   = (const float*)d_in[13];
    float* out = (float*)d_out;

    __half *inr, *pwT, *w1T, *w2T, *combined, *h, *t;
    float *pbias, *gate;
    cudaGetSymbolAddress((void**)&inr, g_inr);
    cudaGetSymbolAddress((void**)&pwT, g_pwT);
    cudaGetSymbolAddress((void**)&pbias, g_pbias);
    cudaGetSymbolAddress((void**)&w1T, g_w1T);
    cudaGetSymbolAddress((void**)&w2T, g_w2T);
    cudaGetSymbolAddress((void**)&combined, g_combined);
    cudaGetSymbolAddress((void**)&gate, g_gate);
    cudaGetSymbolAddress((void**)&h, g_h);
    cudaGetSymbolAddress((void**)&t, g_t);

    cudaFuncSetAttribute(f16_gemm, cudaFuncAttributeMaxDynamicSharedMemorySize, SMEM_BYTES);

    // 1) w1 transpose (no deps)
    transpose_kernel<<<dim3(DD/32, GG/32, NE), 256>>>(w1, nullptr, w1T, GG, DD);
    // 2) proj weights transpose
    transpose_kernel<<<dim3(DD/32, DVV/32, 2), 256>>>(vis_w, txt_w, pwT, DVV, DD);
    // 3) input conversion + bias pack
    {
        long n = 2L * BB * DVV;
        int blocks = (int)((n / 32 + 255) / 256);
        prep_kernel<<<blocks, 256>>>(visual, text, vis_b, txt_b, inr, pbias);
    }
    // 4) batched projection (z=2) -> combined [8192, 2048]  *** profiled ***
    {
        dim3 g(DD / BN, BB / BM, 2);
        f16_gemm<<<g, 256, SMEM_BYTES>>>(inr, (long)BB * DVV, DVV,
                                         pwT, (long)DVV * DD, DVV,
                                         pbias, DD, DVV, 0,
                                         combined, 0, GG, 0, DD);
    }
    // 5) expert GEMM1 + GELU -> h
    {
        dim3 g(DD / BN, BB / BM, NE);
        f16_gemm<<<g, 256, SMEM_BYTES>>>(combined, 0, GG,
                                         w1T, (long)GG * DD, GG,
                                         b1, DD, GG, 1,
                                         h, DD, NE * DD, 0, 0);
    }
    // 6) w2 transpose
    transpose_kernel<<<dim3(DD/32, DD/32, NE), 256>>>(w2, nullptr, w2T, DD, DD);
    // 7) gate softmax
    gate_kernel<<<(BB * 32) / 256, 256>>>(combined, gate_w, gate_b, gate);
    // 8) expert GEMM2 -> t (fp16, normal layout)
    {
        dim3 g(DD / BN, BB / BM, NE);
        f16_gemm<<<g, 256, SMEM_BYTES>>>(h, DD, NE * DD,
                                         w2T, (long)DD * DD, DD,
                                         b2, DD, DD, 2,
                                         t, DD, NE * DD, 0, 0);
    }
    // 9) LayerNorm + gated reduce -> out
    ln_reduce_kernel<<<BB, 256>>>(t, gate, ln_g, ln_b, out);
}

// round 17
// speedup vs baseline: 1.1339x; 1.1339x over previous
#include <cuda_runtime.h>
#include <cuda_fp16.h>
#include <math.h>
#include <cstdint>

#define BB   8192
#define DVV  768
#define NE   8
#define DD   1024
#define GG   2048

// GEMM tiling: CTA 128x256, 8 warps of 64x64, BK=64 halves, 3-stage cp.async
#define BM 128
#define BN 256
#define BK 64
#define STAGES 3
#define PADH 96                         // halves per row; 192B stride == 64 mod 128
#define STAGE_HALVES ((BM + BN) * PADH)
#define SMEM_BYTES (STAGES * STAGE_HALVES * 2)

// 32-group K-permutation: thread c's fragments for TWO k16 steps are 16B-contiguous.
__host__ __device__ __forceinline__ int kperm32(int k) {
    return (k & ~31) | (((k >> 1) & 3) << 3) | (((k >> 4) & 1) << 2)
         | (((k >> 3) & 1) << 1) | (k & 1);
}

// ---------------------------------------------------------------------------
// Scratch (static device globals). GEMM operands stored as k-permuted fp16.
// ---------------------------------------------------------------------------
__device__ __half g_inr[(size_t)2 * BB * DVV];
__device__ __half g_pwT[(size_t)2 * DVV * DD];
__device__ float  g_pbias[2 * DD];
__device__ __half g_w1T[(size_t)NE * GG * DD];
__device__ __half g_w2T[(size_t)NE * DD * DD];
__device__ __half g_combined[(size_t)BB * GG];
__device__ float  g_gate[BB * NE];
__device__ __half g_h[(size_t)BB * NE * DD];
__device__ __half g_t[(size_t)BB * NE * DD];      // fp16 (normal layout)

// ---------------------------------------------------------------------------
// Helpers
// ---------------------------------------------------------------------------
__device__ __forceinline__ uint32_t smem_u32(const void* p) {
    uint32_t a;
    asm("{ .reg .u64 t; cvta.to.shared.u64 t, %1; cvt.u32.u64 %0, t; }" : "=r"(a) : "l"(p));
    return a;
}
__device__ __forceinline__ void cp_async16(uint32_t dst, const void* src) {
    asm volatile("cp.async.cg.shared.global [%0], [%1], 16;" :: "r"(dst), "l"(src));
}
#define CP_COMMIT() asm volatile("cp.async.commit_group;" ::: "memory")
#define CP_WAIT(n)  asm volatile("cp.async.wait_group %0;" :: "n"(n) : "memory")

__device__ __forceinline__ void mma_f16(float& c0, float& c1, float& c2, float& c3,
                                        uint32_t a0, uint32_t a1, uint32_t a2, uint32_t a3,
                                        uint32_t b0, uint32_t b1) {
    asm volatile(
        "mma.sync.aligned.m16n8k16.row.col.f32.f16.f16.f32 "
        "{%0,%1,%2,%3}, {%4,%5,%6,%7}, {%8,%9}, {%0,%1,%2,%3};\n"
        : "+f"(c0), "+f"(c1), "+f"(c2), "+f"(c3)
        : "r"(a0), "r"(a1), "r"(a2), "r"(a3), "r"(b0), "r"(b1));
}

// ---------------------------------------------------------------------------
// fp16 tensor-core GEMM (R15 config, best known): C = act(A@B^T + bias)
// A [M,K] row-major, B [N,K] K-major, both kperm32 fp16.
// CTA 128x256, warp grid 2(m) x 4(n), warp tile 64x64, 3-stage cp.async.
// mode 0: store half(v) kperm cols; mode 1: half(gelu(v)) kperm cols;
// mode 2: store half(v) NORMAL cols (feeds LN)
// ---------------------------------------------------------------------------
__global__ __launch_bounds__(256, 1)
void f16_gemm(const __half* __restrict__ A, long aBatch, int lda,
              const __half* __restrict__ B, long bBatch, int ldb,
              const float* __restrict__ bias, long biasBatch,
              int K, int mode,
              __half* __restrict__ Ch,
              long cBatch, int ldc, int colOfs, int colStride)
{
    extern __shared__ __half smem[];
    const int tid  = threadIdx.x;
    const int wid  = tid >> 5;
    const int lane = tid & 31;
    const int e    = blockIdx.z;
    const int blockRow = blockIdx.y * BM;
    const int blockCol = blockIdx.x * BN;

    A    += (long)e * aBatch;
    B    += (long)e * bBatch;
    bias += (long)e * biasBatch;
    Ch   += (long)e * cBatch;
    const int cOfs = colOfs + e * colStride;

    const uint32_t smem_base = smem_u32(smem);

    const int warpRow = (wid & 1) * 64;
    const int warpCol = (wid >> 1) * 64;
    const int groupID = lane >> 2;
    const int ctig    = lane & 3;

    float acc[4][8][4];
    #pragma unroll
    for (int i = 0; i < 4; i++)
        #pragma unroll
        for (int j = 0; j < 8; j++)
            #pragma unroll
            for (int r = 0; r < 4; r++) acc[i][j][r] = 0.0f;

    const int NC = K / BK;

    const int lm = tid >> 3, lk = tid & 7;
    const __half* aSrc = A + (long)(blockRow + lm) * lda + lk * 8;
    const __half* bSrc = B + (long)(blockCol + lm) * ldb + lk * 8;
    const uint32_t dstOfs = (uint32_t)(lm * PADH + lk * 8) * 2u;

    auto load_stage = [&](int stage, int chunk) {
        const int k0 = chunk * BK;
        const uint32_t aBase = smem_base + (uint32_t)(stage * STAGE_HALVES) * 2u + dstOfs;
        const uint32_t bBase = aBase + (uint32_t)(BM * PADH) * 2u;
        #pragma unroll
        for (int i = 0; i < 4; i++)
            cp_async16(aBase + (uint32_t)(i * 32 * PADH) * 2u,
                       aSrc + (long)(i * 32) * lda + k0);
        #pragma unroll
        for (int i = 0; i < 8; i++)
            cp_async16(bBase + (uint32_t)(i * 32 * PADH) * 2u,
                       bSrc + (long)(i * 32) * ldb + k0);
        CP_COMMIT();
    };

    #pragma unroll
    for (int s = 0; s < STAGES - 1; s++) load_stage(s, s);
    CP_WAIT(STAGES - 2);
    __syncthreads();

    for (int c = 0; c < NC; c++) {
        if (c + STAGES - 1 < NC)
            load_stage((c + STAGES - 1) % STAGES, c + STAGES - 1);

        const int stage = c % STAGES;
        const __half* As = smem + stage * STAGE_HALVES;
        const __half* Bs = As + BM * PADH;

        #pragma unroll
        for (int pr = 0; pr < 2; pr++) {
            const int kb = pr * 32 + 8 * ctig;
            uint4 alo[4], ahi[4], bv[8];
            #pragma unroll
            for (int i = 0; i < 4; i++) {
                const __half* p = As + (warpRow + i * 16 + groupID) * PADH + kb;
                alo[i] = *reinterpret_cast<const uint4*>(p);
                ahi[i] = *reinterpret_cast<const uint4*>(p + 8 * PADH);
            }
            #pragma unroll
            for (int j = 0; j < 8; j++)
                bv[j] = *reinterpret_cast<const uint4*>(
                            Bs + (warpCol + j * 8 + groupID) * PADH + kb);
            #pragma unroll
            for (int i = 0; i < 4; i++)
                #pragma unroll
                for (int j = 0; j < 8; j++)
                    mma_f16(acc[i][j][0], acc[i][j][1], acc[i][j][2], acc[i][j][3],
                            alo[i].x, ahi[i].x, alo[i].y, ahi[i].y,
                            bv[j].x, bv[j].y);
            #pragma unroll
            for (int i = 0; i < 4; i++)
                #pragma unroll
                for (int j = 0; j < 8; j++)
                    mma_f16(acc[i][j][0], acc[i][j][1], acc[i][j][2], acc[i][j][3],
                            alo[i].z, ahi[i].z, alo[i].w, ahi[i].w,
                            bv[j].z, bv[j].w);
        }

        CP_WAIT(STAGES - 2);
        __syncthreads();
    }

    // ---- epilogue ----
    #pragma unroll
    for (int i = 0; i < 4; i++) {
        const int r0 = blockRow + warpRow + i * 16 + groupID;
        #pragma unroll
        for (int j = 0; j < 8; j++) {
            const int gc = blockCol + warpCol + j * 8 + ctig * 2;
            const float b0 = bias[gc], b1 = bias[gc + 1];
            float v0 = acc[i][j][0] + b0;
            float v1 = acc[i][j][1] + b1;
            float v2 = acc[i][j][2] + b0;
            float v3 = acc[i][j][3] + b1;
            if (mode == 2) {
                *reinterpret_cast<__half2*>(Ch + (long)r0 * ldc + cOfs + gc) =
                    __floats2half2_rn(v0, v1);
                *reinterpret_cast<__half2*>(Ch + (long)(r0 + 8) * ldc + cOfs + gc) =
                    __floats2half2_rn(v2, v3);
            } else {
                if (mode == 1) {
                    v0 = 0.5f * v0 * (1.0f + erff(v0 * 0.70710678118654752f));
                    v1 = 0.5f * v1 * (1.0f + erff(v1 * 0.70710678118654752f));
                    v2 = 0.5f * v2 * (1.0f + erff(v2 * 0.70710678118654752f));
                    v3 = 0.5f * v3 * (1.0f + erff(v3 * 0.70710678118654752f));
                }
                const int cp0 = kperm32(cOfs + gc);
                *reinterpret_cast<__half2*>(Ch + (long)r0 * ldc + cp0) =
                    __floats2half2_rn(v0, v1);
                *reinterpret_cast<__half2*>(Ch + (long)(r0 + 8) * ldc + cp0) =
                    __floats2half2_rn(v2, v3);
            }
        }
    }
}

// ---------------------------------------------------------------------------
// Fused prep: convert both inputs to kperm32 fp16, pack proj biases.
// ---------------------------------------------------------------------------
__global__ void prep_kernel(const float* __restrict__ visual,
                            const float* __restrict__ text,
                            const float* __restrict__ vis_b,
                            const float* __restrict__ txt_b,
                            __half* __restrict__ inr,
                            float* __restrict__ pbias)
{
    const long nPer = (long)BB * DVV;
    long t = (long)blockIdx.x * blockDim.x + threadIdx.x;
    if (t < 2 * DD)
        pbias[t] = (t < DD) ? vis_b[t] : txt_b[t - DD];
    long i = t * 32;
    if (i >= 2 * nPer) return;
    const float* src = (i < nPer) ? (visual + i) : (text + (i - nPer));
    float lv[32];
    #pragma unroll
    for (int q = 0; q < 8; q++)
        *reinterpret_cast<float4*>(lv + q * 4) =
            *reinterpret_cast<const float4*>(src + q * 4);
    __half ph[32];
    #pragma unroll
    for (int q = 0; q < 32; q++)
        ph[kperm32(q)] = __float2half_rn(lv[q]);
    #pragma unroll
    for (int q = 0; q < 4; q++)
        *reinterpret_cast<uint4*>(inr + i + q * 8) =
            *reinterpret_cast<uint4*>(ph + q * 8);
}

// ---------------------------------------------------------------------------
// ONE merged transpose launch: w1 (8x), w2 (8x), vis_w+txt_w (2x).
// 1D grid, region dispatch; each block does a 32x32 transpose tile.
// ---------------------------------------------------------------------------
#define TR_W1_BLOCKS (32 * 64 * 8)     // (DD/32) x (GG/32) x NE = 16384
#define TR_W2_BLOCKS (32 * 32 * 8)     // (DD/32) x (DD/32) x NE = 8192
#define TR_PW_BLOCKS (32 * 24 * 2)     // (DD/32) x (DVV/32) x 2 = 1536
#define TR_TOTAL (TR_W1_BLOCKS + TR_W2_BLOCKS + TR_PW_BLOCKS)

__device__ __forceinline__ void tr_tile(const float* __restrict__ W,
                                        __half* __restrict__ WT,
                                        int K, int N, int n0, int k0, int tidx)
{
    __shared__ float tile[32][33];
    const int tx = tidx & 31, ty = tidx >> 5;
    #pragma unroll
    for (int r = 0; r < 4; r++)
        tile[ty + r * 8][tx] = W[(long)(k0 + ty + r * 8) * N + n0 + tx];
    __syncthreads();
    #pragma unroll
    for (int r = 0; r < 4; r++) {
        int n = n0 + ty + r * 8, k = k0 + tx;
        WT[(long)n * K + kperm32(k)] = __float2half_rn(tile[tx][ty + r * 8]);
    }
}

__global__ __launch_bounds__(256)
void transpose_all_kernel(const float* __restrict__ w1,
                          const float* __restrict__ w2,
                          const float* __restrict__ vis_w,
                          const float* __restrict__ txt_w,
                          __half* __restrict__ w1T,
                          __half* __restrict__ w2T,
                          __half* __restrict__ pwT)
{
    int bid = blockIdx.x;
    if (bid < TR_W1_BLOCKS) {
        int x = bid & 31, y = (bid >> 5) & 63, e = bid >> 11;
        tr_tile(w1 + (long)e * GG * DD, w1T + (long)e * GG * DD,
                GG, DD, x * 32, y * 32, threadIdx.x);
    } else if (bid < TR_W1_BLOCKS + TR_W2_BLOCKS) {
        bid -= TR_W1_BLOCKS;
        int x = bid & 31, y = (bid >> 5) & 31, e = bid >> 10;
        tr_tile(w2 + (long)e * DD * DD, w2T + (long)e * DD * DD,
                DD, DD, x * 32, y * 32, threadIdx.x);
    } else {
        bid -= TR_W1_BLOCKS + TR_W2_BLOCKS;
        int x = bid & 31, y = (bid >> 5) % 24, z = bid / (32 * 24);
        const float* W = z ? txt_w : vis_w;
        tr_tile(W, pwT + (long)z * DVV * DD,
                DVV, DD, x * 32, y * 32, threadIdx.x);
    }
}

// ---------------------------------------------------------------------------
// Gate: one warp per row (combined fp16 kperm32; gw logical index)
// ---------------------------------------------------------------------------
__global__ void gate_kernel(const __half* __restrict__ combined,
                            const float* __restrict__ gw,
                            const float* __restrict__ gb,
                            float* __restrict__ gate)
{
    int warp = (blockIdx.x * blockDim.x + threadIdx.x) >> 5;
    int lane = threadIdx.x & 31;
    if (warp >= BB) return;
    const __half* row = combined + (long)warp * GG;

    float acc[NE];
    #pragma unroll
    for (int e = 0; e < NE; e++) acc[e] = 0.0f;

    for (int k = lane; k < GG; k += 32) {
        float x = __half2float(row[kperm32(k)]);
        const float4 w0 = *reinterpret_cast<const float4*>(gw + (long)k * NE);
        const float4 w1 = *reinterpret_cast<const float4*>(gw + (long)k * NE + 4);
        acc[0] = fmaf(x, w0.x, acc[0]);
        acc[1] = fmaf(x, w0.y, acc[1]);
        acc[2] = fmaf(x, w0.z, acc[2]);
        acc[3] = fmaf(x, w0.w, acc[3]);
        acc[4] = fmaf(x, w1.x, acc[4]);
        acc[5] = fmaf(x, w1.y, acc[5]);
        acc[6] = fmaf(x, w1.z, acc[6]);
        acc[7] = fmaf(x, w1.w, acc[7]);
    }
    #pragma unroll
    for (int e = 0; e < NE; e++)
        #pragma unroll
        for (int o = 16; o > 0; o >>= 1)
            acc[e] += __shfl_xor_sync(0xFFFFFFFFu, acc[e], o);

    float m = -1e30f;
    #pragma unroll
    for (int e = 0; e < NE; e++) { acc[e] += gb[e]; m = fmaxf(m, acc[e]); }
    float s = 0.0f;
    #pragma unroll
    for (int e = 0; e < NE; e++) { acc[e] = expf(acc[e] - m); s += acc[e]; }
    float inv = 1.0f / s;
    if (lane < NE) gate[(long)warp * NE + lane] = acc[lane] * inv;
}

// ---------------------------------------------------------------------------
// LayerNorm + gated reduce.  One block per row b; warp w owns expert e=w.
// All 8 experts processed concurrently; ONE __syncthreads.
// ---------------------------------------------------------------------------
__global__ __launch_bounds__(256)
void ln_reduce_kernel(const __half* __restrict__ t,
                      const float* __restrict__ gate,
                      const float* __restrict__ ln_g,
                      const float* __restrict__ ln_b,
                      float* __restrict__ out)
{
    const int b = blockIdx.x;
    const int wid = threadIdx.x >> 5, lane = threadIdx.x & 31;

    __shared__ float4 contrib[NE][DD / 4];     // 32 KB

    const __half* row = t + ((long)b * NE + wid) * DD;

    // load 32 elems per lane: cols lane*4 + q*128 + j
    float xv[32];
    #pragma unroll
    for (int q = 0; q < 8; q++) {
        uint2 raw = *reinterpret_cast<const uint2*>(row + lane * 4 + q * 128);
        float2 f01 = __half22float2(*reinterpret_cast<__half2*>(&raw.x));
        float2 f23 = __half22float2(*reinterpret_cast<__half2*>(&raw.y));
        xv[q * 4 + 0] = f01.x; xv[q * 4 + 1] = f01.y;
        xv[q * 4 + 2] = f23.x; xv[q * 4 + 3] = f23.y;
    }
    float s = 0.f, ss = 0.f;
    #pragma unroll
    for (int q = 0; q < 32; q++) { s += xv[q]; ss = fmaf(xv[q], xv[q], ss); }
    #pragma unroll
    for (int o2 = 16; o2 > 0; o2 >>= 1) {
        s  += __shfl_xor_sync(0xFFFFFFFFu, s, o2);
        ss += __shfl_xor_sync(0xFFFFFFFFu, ss, o2);
    }
    const float mu   = s * (1.0f / DD);
    const float var  = ss * (1.0f / DD) - mu * mu;
    const float rstd = rsqrtf(var + 1e-5f);
    const float p    = gate[(long)b * NE + wid];

    #pragma unroll
    for (int q = 0; q < 8; q++) {
        const int col = lane * 4 + q * 128;
        const float4 g4 = *reinterpret_cast<const float4*>(ln_g + (long)wid * DD + col);
        const float4 b4 = *reinterpret_cast<const float4*>(ln_b + (long)wid * DD + col);
        float4 v;
        v.x = p * fmaf((xv[q*4+0] - mu) * rstd, g4.x, b4.x);
        v.y = p * fmaf((xv[q*4+1] - mu) * rstd, g4.y, b4.y);
        v.z = p * fmaf((xv[q*4+2] - mu) * rstd, g4.z, b4.z);
        v.w = p * fmaf((xv[q*4+3] - mu) * rstd, g4.w, b4.w);
        contrib[wid][lane + q * 32] = v;
    }
    __syncthreads();

    // final: thread tid sums 8 experts for its 4 columns
    const int tid = threadIdx.x;
    float4 o = contrib[0][tid];
    #pragma unroll
    for (int e = 1; e < NE; e++) {
        float4 c = contrib[e][tid];
        o.x += c.x; o.y += c.y; o.z += c.z; o.w += c.w;
    }
    *reinterpret_cast<float4*>(out + (long)b * DD + tid * 4) = o;
}

// ---------------------------------------------------------------------------
// Launch.  The 4th launch is the projection GEMM (the one ncu captures).
// ---------------------------------------------------------------------------
extern "C" void kernel_launch(void* const* d_in, const int* in_sizes, int n_in,
                              void* d_out, int out_size)
{
    const float* visual = (const float*)d_in[0];
    const float* text   = (const float*)d_in[1];
    const float* vis_w  = (const float*)d_in[2];
    const float* vis_b  = (const float*)d_in[3];
    const float* txt_w  = (const float*)d_in[4];
    const float* txt_b  = (const float*)d_in[5];
    const float* gate_w = (const float*)d_in[6];
    const float* gate_b = (const float*)d_in[7];
    const float* w1     = (const float*)d_in[8];
    const float* b1     = (const float*)d_in[9];
    const float* w2     = (const float*)d_in[10];
    const float* b2     = (const float*)d_in[11];
    const float* ln_g   = (const float*)d_in[12];
    const float* ln_b   = (const float*)d_in[13];
    float* out = (float*)d_out;

    __half *inr, *pwT, *w1T, *w2T, *combined, *h, *t;
    float *pbias, *gate;
    cudaGetSymbolAddress((void**)&inr, g_inr);
    cudaGetSymbolAddress((void**)&pwT, g_pwT);
    cudaGetSymbolAddress((void**)&pbias, g_pbias);
    cudaGetSymbolAddress((void**)&w1T, g_w1T);
    cudaGetSymbolAddress((void**)&w2T, g_w2T);
    cudaGetSymbolAddress((void**)&combined, g_combined);
    cudaGetSymbolAddress((void**)&gate, g_gate);
    cudaGetSymbolAddress((void**)&h, g_h);
    cudaGetSymbolAddress((void**)&t, g_t);

    cudaFuncSetAttribute(f16_gemm, cudaFuncAttributeMaxDynamicSharedMemorySize, SMEM_BYTES);

    // 1) all weight transposes in ONE launch
    transpose_all_kernel<<<TR_TOTAL, 256>>>(w1, w2, vis_w, txt_w, w1T, w2T, pwT);
    // 2) input conversion + bias pack
    {
        long n = 2L * BB * DVV;
        int blocks = (int)((n / 32 + 255) / 256);
        prep_kernel<<<blocks, 256>>>(visual, text, vis_b, txt_b, inr, pbias);
    }
    // 3) (slot kept minimal so #4 is the proj GEMM for ncu)
    //    -- nothing needed here; gate moved after GEMM1.
    //    dummy-free: issue gate later.
    // 4) batched projection (z=2) -> combined [8192, 2048]
    {
        dim3 g(DD / BN, BB / BM, 2);
        f16_gemm<<<g, 256, SMEM_BYTES>>>(inr, (long)BB * DVV, DVV,
                                         pwT, (long)DVV * DD, DVV,
                                         pbias, DD, DVV, 0,
                                         combined, 0, GG, 0, DD);
        // NOTE: this is launch #3 now; ncu -s5 profiles launch #6 (GEMM1) —
        // even better signal.
    }
    // 5) expert GEMM1 + GELU -> h
    {
        dim3 g(DD / BN, BB / BM, NE);
        f16_gemm<<<g, 256, SMEM_BYTES>>>(combined, 0, GG,
                                         w1T, (long)GG * DD, GG,
                                         b1, DD, GG, 1,
                                         h, DD, NE * DD, 0, 0);
    }
    // 6) gate softmax
    gate_kernel<<<(BB * 32) / 256, 256>>>(combined, gate_w, gate_b, gate);
    // 7) expert GEMM2 -> t (fp16, normal layout)
    {
        dim3 g(DD / BN, BB / BM, NE);
        f16_gemm<<<g, 256, SMEM_BYTES>>>(h, DD, NE * DD,
                                         w2T, (long)DD * DD, DD,
                                         b2, DD, DD, 2,
                                         t, DD, NE * DD, 0, 0);
    }
    // 8) LayerNorm + gated reduce -> out
    ln_reduce_kernel<<<BB, 256>>>(t, gate, ln_g, ln_b, out);
}